// round 2
// baseline (speedup 1.0000x reference)
#include <cuda_runtime.h>
#include <math.h>

#define NODES 100000
#define DIMM  256

// ---------------- scratch (device globals; no allocation allowed) ----------------
__device__ float g_agg[(size_t)NODES * DIMM];
__device__ float g_z  [(size_t)NODES * DIMM];
__device__ float g_h  [(size_t)NODES * DIMM];
__device__ float g_bnsum[DIMM];
__device__ float g_bnsq [DIMM];

// ---------------- zero ----------------
__global__ void zero_kernel(float4* __restrict__ p, size_t n4) {
    size_t i = (size_t)blockIdx.x * blockDim.x + threadIdx.x;
    size_t stride = (size_t)gridDim.x * blockDim.x;
    float4 z = make_float4(0.f, 0.f, 0.f, 0.f);
    for (; i < n4; i += stride) p[i] = z;
}

// ---------------- scatter-sum aggregation: agg[dst] += h[src] ----------------
__global__ void scatter_kernel(const float* __restrict__ h,
                               const int* __restrict__ src,
                               const int* __restrict__ dst,
                               float* __restrict__ agg,
                               int nedges, int D) {
    int warp  = (blockIdx.x * blockDim.x + threadIdx.x) >> 5;
    int lane  = threadIdx.x & 31;
    int nwarp = (gridDim.x * blockDim.x) >> 5;
    for (int e = warp; e < nedges; e += nwarp) {
        int s = __ldg(&src[e]);
        int d = __ldg(&dst[e]);
        const float* hs = h + (size_t)s * D;
        float*       ad = agg + (size_t)d * D;
        for (int f = lane; f < D; f += 32)
            atomicAdd(ad + f, __ldg(hs + f));
    }
}

// ---------------- tiled fp32 GEMM: C = op(A [+A2]) @ B + bias ----------------
// A: [M,K] row-major, B: [K,N] row-major, C: [M,N]. BM=BN=128, BK=8, 256 thr.
template<bool ADD2, bool RELU>
__global__ __launch_bounds__(256, 2)
void gemm_kernel(const float* __restrict__ A, const float* __restrict__ A2,
                 const float* __restrict__ B, const float* __restrict__ bias,
                 float* __restrict__ C, int M, int K, int N) {
    __shared__ float As[8][128];
    __shared__ float Bs[8][128];

    const int tid  = threadIdx.x;
    const int row0 = blockIdx.x * 128;
    const int col0 = blockIdx.y * 128;

    const int ty = tid >> 4;        // 0..15 -> 8 rows each
    const int tx = tid & 15;        // 0..15 -> 8 cols each

    const int arow = tid >> 1;       // 0..127
    const int acol = (tid & 1) * 4;  // 0 or 4
    const int brow = tid >> 5;       // 0..7
    const int bcol = (tid & 31) * 4; // 0..124

    float acc[8][8];
    #pragma unroll
    for (int i = 0; i < 8; i++)
        #pragma unroll
        for (int j = 0; j < 8; j++) acc[i][j] = 0.f;

    for (int k0 = 0; k0 < K; k0 += 8) {
        int gr = row0 + arow;
        float4 av = make_float4(0.f, 0.f, 0.f, 0.f);
        if (gr < M) {
            av = *(const float4*)(A + (size_t)gr * K + k0 + acol);
            if (ADD2) {
                float4 bv = *(const float4*)(A2 + (size_t)gr * K + k0 + acol);
                av.x += bv.x; av.y += bv.y; av.z += bv.z; av.w += bv.w;
            }
        }
        As[acol + 0][arow] = av.x;
        As[acol + 1][arow] = av.y;
        As[acol + 2][arow] = av.z;
        As[acol + 3][arow] = av.w;

        *(float4*)&Bs[brow][bcol] =
            *(const float4*)(B + (size_t)(k0 + brow) * N + col0 + bcol);

        __syncthreads();

        #pragma unroll
        for (int k = 0; k < 8; k++) {
            float a[8], b[8];
            *(float4*)&a[0] = *(const float4*)&As[k][ty * 8];
            *(float4*)&a[4] = *(const float4*)&As[k][ty * 8 + 4];
            *(float4*)&b[0] = *(const float4*)&Bs[k][tx * 8];
            *(float4*)&b[4] = *(const float4*)&Bs[k][tx * 8 + 4];
            #pragma unroll
            for (int i = 0; i < 8; i++)
                #pragma unroll
                for (int j = 0; j < 8; j++)
                    acc[i][j] = fmaf(a[i], b[j], acc[i][j]);
        }
        __syncthreads();
    }

    float bv[8];
    #pragma unroll
    for (int j = 0; j < 8; j++) bv[j] = __ldg(&bias[col0 + tx * 8 + j]);

    #pragma unroll
    for (int i = 0; i < 8; i++) {
        int gr = row0 + ty * 8 + i;
        if (gr < M) {
            #pragma unroll
            for (int j = 0; j < 8; j++) {
                float v = acc[i][j] + bv[j];
                if (RELU) v = fmaxf(v, 0.f);
                acc[i][j] = v;
            }
            *(float4*)(C + (size_t)gr * N + col0 + tx * 8)     = *(float4*)&acc[i][0];
            *(float4*)(C + (size_t)gr * N + col0 + tx * 8 + 4) = *(float4*)&acc[i][4];
        }
    }
}

// ---------------- batchnorm stats (per-column sum / sumsq) ----------------
__global__ void bn_stats_kernel(const float* __restrict__ h, int M) {
    int col = threadIdx.x;  // 256 threads, one per column
    int nb  = gridDim.x;
    int rpb = (M + nb - 1) / nb;
    int r0  = blockIdx.x * rpb;
    int r1  = min(r0 + rpb, M);
    float s = 0.f, q = 0.f;
    for (int r = r0; r < r1; r++) {
        float v = h[(size_t)r * DIMM + col];
        s += v;
        q = fmaf(v, v, q);
    }
    atomicAdd(&g_bnsum[col], s);
    atomicAdd(&g_bnsq[col],  q);
}

// ---------------- batchnorm apply (in place) ----------------
__global__ void bn_apply_kernel(float* __restrict__ h, const float* __restrict__ gamma,
                                const float* __restrict__ beta, int M) {
    __shared__ float sc[DIMM], sh[DIMM];
    int t = threadIdx.x;
    if (t < DIMM) {
        float m   = g_bnsum[t] / (float)M;
        float v   = g_bnsq[t] / (float)M - m * m;
        float inv = rsqrtf(v + 1e-5f);
        float s   = gamma[t] * inv;
        sc[t] = s;
        sh[t] = beta[t] - m * s;
    }
    __syncthreads();
    size_t n4 = (size_t)M * DIMM / 4;
    float4* h4 = (float4*)h;
    for (size_t i = (size_t)blockIdx.x * blockDim.x + t; i < n4;
         i += (size_t)gridDim.x * blockDim.x) {
        int cb = (int)((i * 4) & (DIMM - 1));
        float4 v = h4[i];
        v.x = fmaf(v.x, sc[cb + 0], sh[cb + 0]);
        v.y = fmaf(v.y, sc[cb + 1], sh[cb + 1]);
        v.z = fmaf(v.z, sc[cb + 2], sh[cb + 2]);
        v.w = fmaf(v.w, sc[cb + 3], sh[cb + 3]);
        h4[i] = v;
    }
}

// ---------------- final fc (256->16) + log_softmax, one warp per row ----------------
__global__ void fc_lsm_kernel(const float* __restrict__ h, const float* __restrict__ wfc,
                              const float* __restrict__ bfc, float* __restrict__ out, int M) {
    __shared__ float ws[DIMM * 16];
    for (int i = threadIdx.x; i < DIMM * 16; i += blockDim.x) ws[i] = wfc[i];
    __syncthreads();

    int warp = threadIdx.x >> 5;
    int lane = threadIdx.x & 31;
    int c    = lane & 15;
    int half = lane >> 4;
    int row  = blockIdx.x * 8 + warp;
    if (row >= M) return;

    const float* hr = h + (size_t)row * DIMM;
    float acc = 0.f;
    int kbase = half * 128;
    #pragma unroll 8
    for (int k = 0; k < 128; k++)
        acc = fmaf(hr[kbase + k], ws[(kbase + k) * 16 + c], acc);
    acc += __shfl_xor_sync(0xffffffffu, acc, 16);

    float logit = acc + bfc[c];
    float m = logit;
    #pragma unroll
    for (int off = 8; off; off >>= 1)
        m = fmaxf(m, __shfl_xor_sync(0xffffffffu, m, off));
    float e = expf(logit - m);
    float s = e;
    #pragma unroll
    for (int off = 8; off; off >>= 1)
        s += __shfl_xor_sync(0xffffffffu, s, off);
    float r = logit - m - logf(s);
    if (lane < 16) out[(size_t)row * 16 + c] = r;
}

// ---------------- launch sequence ----------------
static inline void zero_buf(float* p, size_t nfloats) {
    size_t n4 = nfloats / 4;
    int blocks = (int)((n4 + 255) / 256);
    if (blocks > 8192) blocks = 8192;
    zero_kernel<<<blocks, 256>>>((float4*)p, n4);
}

extern "C" void kernel_launch(void* const* d_in, const int* in_sizes, int n_in,
                              void* d_out, int out_size) {
    const float* x   = (const float*)d_in[0];
    const int*   ei  = (const int*)d_in[1];   // int64 in reference -> delivered as int32
    const float* w1a = (const float*)d_in[2];  const float* b1a = (const float*)d_in[3];
    const float* w1b = (const float*)d_in[4];  const float* b1b = (const float*)d_in[5];
    const float* g1  = (const float*)d_in[6];  const float* be1 = (const float*)d_in[7];
    const float* w2a = (const float*)d_in[8];  const float* b2a = (const float*)d_in[9];
    const float* w2b = (const float*)d_in[10]; const float* b2b = (const float*)d_in[11];
    const float* g2  = (const float*)d_in[12]; const float* be2 = (const float*)d_in[13];
    const float* w3a = (const float*)d_in[14]; const float* b3a = (const float*)d_in[15];
    const float* w3b = (const float*)d_in[16]; const float* b3b = (const float*)d_in[17];
    const float* wfc = (const float*)d_in[18]; const float* bfc = (const float*)d_in[19];
    float* out = (float*)d_out;

    const int M = NODES;
    const int E = in_sizes[1] / 2;
    const int* src = ei;
    const int* dst = ei + E;

    float *agg, *z, *h, *bns, *bnq;
    cudaGetSymbolAddress((void**)&agg, g_agg);
    cudaGetSymbolAddress((void**)&z,   g_z);
    cudaGetSymbolAddress((void**)&h,   g_h);
    cudaGetSymbolAddress((void**)&bns, g_bnsum);
    cudaGetSymbolAddress((void**)&bnq, g_bnsq);

    dim3 ggrid((M + 127) / 128, 2);   // N = 256 -> 2 col tiles
    const int SCAT_BLOCKS = 2368;
    const int BN_BLOCKS = 512;

    // ---- conv1 (K=128 aggregation on x) ----
    zero_buf(agg, (size_t)M * 128);
    scatter_kernel<<<SCAT_BLOCKS, 256>>>(x, src, dst, agg, E, 128);
    gemm_kernel<true,  true ><<<ggrid, 256>>>(x, agg, w1a, b1a, z, M, 128, 256);
    gemm_kernel<false, true ><<<ggrid, 256>>>(z, nullptr, w1b, b1b, h, M, 256, 256);
    zero_buf(bns, DIMM); zero_buf(bnq, DIMM);
    bn_stats_kernel<<<BN_BLOCKS, 256>>>(h, M);
    bn_apply_kernel<<<4096, 256>>>(h, g1, be1, M);

    // ---- conv2 ----
    zero_buf(agg, (size_t)M * 256);
    scatter_kernel<<<SCAT_BLOCKS, 256>>>(h, src, dst, agg, E, 256);
    gemm_kernel<true,  true ><<<ggrid, 256>>>(h, agg, w2a, b2a, z, M, 256, 256);
    gemm_kernel<false, true ><<<ggrid, 256>>>(z, nullptr, w2b, b2b, h, M, 256, 256);
    zero_buf(bns, DIMM); zero_buf(bnq, DIMM);
    bn_stats_kernel<<<BN_BLOCKS, 256>>>(h, M);
    bn_apply_kernel<<<4096, 256>>>(h, g2, be2, M);

    // ---- conv3 ----
    zero_buf(agg, (size_t)M * 256);
    scatter_kernel<<<SCAT_BLOCKS, 256>>>(h, src, dst, agg, E, 256);
    gemm_kernel<true,  true ><<<ggrid, 256>>>(h, agg, w3a, b3a, z, M, 256, 256);
    gemm_kernel<false, true ><<<ggrid, 256>>>(z, nullptr, w3b, b3b, h, M, 256, 256);

    // ---- fc + log_softmax ----
    fc_lsm_kernel<<<(M + 7) / 8, 256>>>(h, wfc, bfc, out, M);
}

// round 3
// speedup vs baseline: 1.4732x; 1.4732x over previous
#include <cuda_runtime.h>
#include <math.h>

#define NODES 100000
#define EMAX  3200000
#define DIMM  256

// ---------------- scratch (device globals; no allocation allowed) ----------------
__device__ float g_agg[(size_t)NODES * DIMM];
__device__ float g_z  [(size_t)NODES * DIMM];
__device__ float g_h  [(size_t)NODES * DIMM];
__device__ float g_bnsum[DIMM];
__device__ float g_bnsq [DIMM];
// CSR scratch
__device__ int g_deg[NODES];
__device__ int g_off[NODES];
__device__ int g_pos[NODES];
__device__ int g_esrc[EMAX];
__device__ int g_bsum[256];

#define SCAN_CHUNK 512
#define SCAN_NB    196   // ceil(100000/512)

// ---------------- zero ----------------
__global__ void zero_kernel(float4* __restrict__ p, size_t n4) {
    size_t i = (size_t)blockIdx.x * blockDim.x + threadIdx.x;
    size_t stride = (size_t)gridDim.x * blockDim.x;
    float4 z = make_float4(0.f, 0.f, 0.f, 0.f);
    for (; i < n4; i += stride) p[i] = z;
}

// ---------------- CSR build ----------------
__global__ void hist_kernel(const int* __restrict__ dst, int E) {
    int i = blockIdx.x * blockDim.x + threadIdx.x;
    int stride = gridDim.x * blockDim.x;
    for (; i < E; i += stride) atomicAdd(&g_deg[dst[i]], 1);
}

__global__ void scan_blocksum_kernel() {
    int b = blockIdx.x, t = threadIdx.x;
    int i0 = b * SCAN_CHUNK + 2 * t;
    int v = 0;
    if (i0 < NODES)     v += g_deg[i0];
    if (i0 + 1 < NODES) v += g_deg[i0 + 1];
    __shared__ int sm[256];
    sm[t] = v; __syncthreads();
    for (int s = 128; s; s >>= 1) { if (t < s) sm[t] += sm[t + s]; __syncthreads(); }
    if (t == 0) g_bsum[b] = sm[0];
}

__global__ void scan_bases_kernel() {
    int t = threadIdx.x;
    __shared__ int sm[256];
    int orig = (t < SCAN_NB) ? g_bsum[t] : 0;
    sm[t] = orig; __syncthreads();
    for (int off = 1; off < 256; off <<= 1) {
        int v = (t >= off) ? sm[t - off] : 0;
        __syncthreads();
        sm[t] += v;
        __syncthreads();
    }
    if (t < SCAN_NB) g_bsum[t] = sm[t] - orig;   // exclusive
}

__global__ void scan_final_kernel() {
    int b = blockIdx.x, t = threadIdx.x;
    int i0 = b * SCAN_CHUNK + 2 * t;
    int d0 = (i0 < NODES) ? g_deg[i0] : 0;
    int d1 = (i0 + 1 < NODES) ? g_deg[i0 + 1] : 0;
    int pair = d0 + d1;
    __shared__ int sm[256];
    sm[t] = pair; __syncthreads();
    int orig = pair;
    for (int off = 1; off < 256; off <<= 1) {
        int v = (t >= off) ? sm[t - off] : 0;
        __syncthreads();
        sm[t] += v;
        __syncthreads();
    }
    int excl = sm[t] - orig + g_bsum[b];
    if (i0 < NODES)     { g_off[i0] = excl;          g_pos[i0] = excl; }
    if (i0 + 1 < NODES) { g_off[i0 + 1] = excl + d0; g_pos[i0 + 1] = excl + d0; }
}

__global__ void bucket_kernel(const int* __restrict__ src, const int* __restrict__ dst, int E) {
    int i = blockIdx.x * blockDim.x + threadIdx.x;
    int stride = gridDim.x * blockDim.x;
    for (; i < E; i += stride) {
        int d = dst[i];
        int p = atomicAdd(&g_pos[d], 1);
        g_esrc[p] = src[i];
    }
}

// ---------------- atomic-free gather aggregate: agg[n] = sum_{e in CSR(n)} h[src(e)] ----------------
template<int D>
__global__ void agg_kernel(const float* __restrict__ h, float* __restrict__ agg) {
    int w    = (blockIdx.x * blockDim.x + threadIdx.x) >> 5;
    int lane = threadIdx.x & 31;
    int nw   = (gridDim.x * blockDim.x) >> 5;
    const float4* hp = (const float4*)h;
    for (int node = w; node < NODES; node += nw) {
        int beg = g_off[node];
        int cnt = g_deg[node];
        float4 a0 = make_float4(0.f, 0.f, 0.f, 0.f);
        float4 a1 = a0;
        #pragma unroll 2
        for (int i = 0; i < cnt; i++) {
            int s = __ldg(&g_esrc[beg + i]);
            const float4* r = hp + (size_t)s * (D / 4);
            float4 v = __ldg(&r[lane]);
            a0.x += v.x; a0.y += v.y; a0.z += v.z; a0.w += v.w;
            if (D == 256) {
                float4 v1 = __ldg(&r[lane + 32]);
                a1.x += v1.x; a1.y += v1.y; a1.z += v1.z; a1.w += v1.w;
            }
        }
        float4* ap = (float4*)agg + (size_t)node * (D / 4);
        ap[lane] = a0;
        if (D == 256) ap[lane + 32] = a1;
    }
}

// ---------------- 3xTF32 tensor-core GEMM ----------------
// C[M,N] = op(A [+A2]) @ B + bias (+ReLU). A row-major [M,K], B row-major [K,N].
// Block tile 128x64, BK=16, 256 threads (8 warps as 4x2), warp tile 32x32.
__device__ __forceinline__ unsigned f2tf32(float x) {
    unsigned r; asm("cvt.rna.tf32.f32 %0, %1;" : "=r"(r) : "f"(x)); return r;
}
__device__ __forceinline__ void mma_tf32(float* c, const unsigned* a, const unsigned* b) {
    asm volatile(
        "mma.sync.aligned.m16n8k8.row.col.f32.tf32.tf32.f32 "
        "{%0,%1,%2,%3}, {%4,%5,%6,%7}, {%8,%9}, {%0,%1,%2,%3};"
        : "+f"(c[0]), "+f"(c[1]), "+f"(c[2]), "+f"(c[3])
        : "r"(a[0]), "r"(a[1]), "r"(a[2]), "r"(a[3]), "r"(b[0]), "r"(b[1]));
}

#define SA 20   // As row stride (floats): 20 mod 32 ensures conflict-free frag loads
#define SB 72   // Bs row stride (floats): 72 mod 32 = 8, conflict-free

template<bool ADD2, bool RELU>
__global__ __launch_bounds__(256, 2)
void gemm_tc_kernel(const float* __restrict__ A, const float* __restrict__ A2,
                    const float* __restrict__ B, const float* __restrict__ bias,
                    float* __restrict__ C, int M, int K, int N) {
    __shared__ float As_h[128 * SA];
    __shared__ float As_l[128 * SA];
    __shared__ float Bs_h[16 * SB];
    __shared__ float Bs_l[16 * SB];

    const int tid  = threadIdx.x;
    const int lane = tid & 31;
    const int wid  = tid >> 5;
    const int wm   = wid & 3;       // 0..3 -> m offset
    const int wn   = wid >> 2;      // 0..1 -> n offset
    const int row0 = blockIdx.x * 128;
    const int col0 = blockIdx.y * 64;

    const int lr = lane >> 2;       // 0..7
    const int lc = lane & 3;        // 0..3

    float acc[2][4][4];
    #pragma unroll
    for (int mt = 0; mt < 2; mt++)
        #pragma unroll
        for (int nt = 0; nt < 4; nt++)
            #pragma unroll
            for (int i = 0; i < 4; i++) acc[mt][nt][i] = 0.f;

    // A tile loaders: thread -> row tid>>1, cols (tid&1)*8 .. +7 (2 float4)
    const int ar = tid >> 1;
    const int ac = (tid & 1) * 8;
    // B tile loaders: thread -> row tid>>4 (0..15), cols (tid&15)*4
    const int br = tid >> 4;
    const int bc = (tid & 15) * 4;

    for (int k0 = 0; k0 < K; k0 += 16) {
        // ---- load + split A ----
        {
            int gr = row0 + ar;
            float va[8];
            if (gr < M) {
                const float* ap = A + (size_t)gr * K + k0 + ac;
                float4 v0 = *(const float4*)(ap);
                float4 v1 = *(const float4*)(ap + 4);
                if (ADD2) {
                    const float* a2p = A2 + (size_t)gr * K + k0 + ac;
                    float4 u0 = *(const float4*)(a2p);
                    float4 u1 = *(const float4*)(a2p + 4);
                    v0.x += u0.x; v0.y += u0.y; v0.z += u0.z; v0.w += u0.w;
                    v1.x += u1.x; v1.y += u1.y; v1.z += u1.z; v1.w += u1.w;
                }
                va[0]=v0.x; va[1]=v0.y; va[2]=v0.z; va[3]=v0.w;
                va[4]=v1.x; va[5]=v1.y; va[6]=v1.z; va[7]=v1.w;
            } else {
                #pragma unroll
                for (int i = 0; i < 8; i++) va[i] = 0.f;
            }
            float* dh = &As_h[ar * SA + ac];
            float* dl = &As_l[ar * SA + ac];
            #pragma unroll
            for (int i = 0; i < 8; i++) {
                unsigned hi = f2tf32(va[i]);
                float hf = __uint_as_float(hi);
                unsigned lo = f2tf32(va[i] - hf);
                dh[i] = hf;
                dl[i] = __uint_as_float(lo);
            }
        }
        // ---- load + split B ----
        {
            const float* bp = B + (size_t)(k0 + br) * N + col0 + bc;
            float4 v = *(const float4*)bp;
            float vb[4] = {v.x, v.y, v.z, v.w};
            float* dh = &Bs_h[br * SB + bc];
            float* dl = &Bs_l[br * SB + bc];
            #pragma unroll
            for (int i = 0; i < 4; i++) {
                unsigned hi = f2tf32(vb[i]);
                float hf = __uint_as_float(hi);
                unsigned lo = f2tf32(vb[i] - hf);
                dh[i] = hf;
                dl[i] = __uint_as_float(lo);
            }
        }
        __syncthreads();

        #pragma unroll
        for (int ks = 0; ks < 16; ks += 8) {
            unsigned ah[2][4], al[2][4], bh[4][2], bl[4][2];
            #pragma unroll
            for (int mt = 0; mt < 2; mt++) {
                int rbase = (wm * 32 + mt * 16 + lr) * SA + ks + lc;
                ah[mt][0] = __float_as_uint(As_h[rbase]);
                ah[mt][1] = __float_as_uint(As_h[rbase + 8 * SA]);
                ah[mt][2] = __float_as_uint(As_h[rbase + 4]);
                ah[mt][3] = __float_as_uint(As_h[rbase + 8 * SA + 4]);
                al[mt][0] = __float_as_uint(As_l[rbase]);
                al[mt][1] = __float_as_uint(As_l[rbase + 8 * SA]);
                al[mt][2] = __float_as_uint(As_l[rbase + 4]);
                al[mt][3] = __float_as_uint(As_l[rbase + 8 * SA + 4]);
            }
            #pragma unroll
            for (int nt = 0; nt < 4; nt++) {
                int bbase = (ks + lc) * SB + wn * 32 + nt * 8 + lr;
                bh[nt][0] = __float_as_uint(Bs_h[bbase]);
                bh[nt][1] = __float_as_uint(Bs_h[bbase + 4 * SB]);
                bl[nt][0] = __float_as_uint(Bs_l[bbase]);
                bl[nt][1] = __float_as_uint(Bs_l[bbase + 4 * SB]);
            }
            #pragma unroll
            for (int mt = 0; mt < 2; mt++)
                #pragma unroll
                for (int nt = 0; nt < 4; nt++) {
                    mma_tf32(acc[mt][nt], ah[mt], bh[nt]);
                    mma_tf32(acc[mt][nt], ah[mt], bl[nt]);
                    mma_tf32(acc[mt][nt], al[mt], bh[nt]);
                }
        }
        __syncthreads();
    }

    // ---- epilogue: bias (+relu), write ----
    #pragma unroll
    for (int mt = 0; mt < 2; mt++) {
        int gr0 = row0 + wm * 32 + mt * 16 + lr;
        #pragma unroll
        for (int nt = 0; nt < 4; nt++) {
            int cg = col0 + wn * 32 + nt * 8 + lc * 2;
            float b0 = __ldg(&bias[cg]);
            float b1 = __ldg(&bias[cg + 1]);
            float v0 = acc[mt][nt][0] + b0;
            float v1 = acc[mt][nt][1] + b1;
            float v2 = acc[mt][nt][2] + b0;
            float v3 = acc[mt][nt][3] + b1;
            if (RELU) {
                v0 = fmaxf(v0, 0.f); v1 = fmaxf(v1, 0.f);
                v2 = fmaxf(v2, 0.f); v3 = fmaxf(v3, 0.f);
            }
            if (gr0 < M)     *(float2*)(C + (size_t)gr0 * N + cg)       = make_float2(v0, v1);
            if (gr0 + 8 < M) *(float2*)(C + (size_t)(gr0 + 8) * N + cg) = make_float2(v2, v3);
        }
    }
}

// ---------------- batchnorm stats (per-column sum / sumsq) ----------------
__global__ void bn_stats_kernel(const float* __restrict__ h, int M) {
    int col = threadIdx.x;
    int nb  = gridDim.x;
    int rpb = (M + nb - 1) / nb;
    int r0  = blockIdx.x * rpb;
    int r1  = min(r0 + rpb, M);
    float s = 0.f, q = 0.f;
    for (int r = r0; r < r1; r++) {
        float v = h[(size_t)r * DIMM + col];
        s += v;
        q = fmaf(v, v, q);
    }
    atomicAdd(&g_bnsum[col], s);
    atomicAdd(&g_bnsq[col],  q);
}

// ---------------- batchnorm apply (in place) ----------------
__global__ void bn_apply_kernel(float* __restrict__ h, const float* __restrict__ gamma,
                                const float* __restrict__ beta, int M) {
    __shared__ float sc[DIMM], sh[DIMM];
    int t = threadIdx.x;
    if (t < DIMM) {
        float m   = g_bnsum[t] / (float)M;
        float v   = g_bnsq[t] / (float)M - m * m;
        float inv = rsqrtf(v + 1e-5f);
        float s   = gamma[t] * inv;
        sc[t] = s;
        sh[t] = beta[t] - m * s;
    }
    __syncthreads();
    size_t n4 = (size_t)M * DIMM / 4;
    float4* h4 = (float4*)h;
    for (size_t i = (size_t)blockIdx.x * blockDim.x + t; i < n4;
         i += (size_t)gridDim.x * blockDim.x) {
        int cb = (int)((i * 4) & (DIMM - 1));
        float4 v = h4[i];
        v.x = fmaf(v.x, sc[cb + 0], sh[cb + 0]);
        v.y = fmaf(v.y, sc[cb + 1], sh[cb + 1]);
        v.z = fmaf(v.z, sc[cb + 2], sh[cb + 2]);
        v.w = fmaf(v.w, sc[cb + 3], sh[cb + 3]);
        h4[i] = v;
    }
}

// ---------------- final fc (256->16) + log_softmax, one warp per row ----------------
__global__ void fc_lsm_kernel(const float* __restrict__ h, const float* __restrict__ wfc,
                              const float* __restrict__ bfc, float* __restrict__ out, int M) {
    __shared__ float ws[DIMM * 16];
    for (int i = threadIdx.x; i < DIMM * 16; i += blockDim.x) ws[i] = wfc[i];
    __syncthreads();

    int warp = threadIdx.x >> 5;
    int lane = threadIdx.x & 31;
    int c    = lane & 15;
    int half = lane >> 4;
    int row  = blockIdx.x * 8 + warp;
    if (row >= M) return;

    const float* hr = h + (size_t)row * DIMM;
    float acc = 0.f;
    int kbase = half * 128;
    #pragma unroll 8
    for (int k = 0; k < 128; k++)
        acc = fmaf(hr[kbase + k], ws[(kbase + k) * 16 + c], acc);
    acc += __shfl_xor_sync(0xffffffffu, acc, 16);

    float logit = acc + bfc[c];
    float m = logit;
    #pragma unroll
    for (int off = 8; off; off >>= 1)
        m = fmaxf(m, __shfl_xor_sync(0xffffffffu, m, off));
    float e = expf(logit - m);
    float s = e;
    #pragma unroll
    for (int off = 8; off; off >>= 1)
        s += __shfl_xor_sync(0xffffffffu, s, off);
    float r = logit - m - logf(s);
    if (lane < 16) out[(size_t)row * 16 + c] = r;
}

// ---------------- launch sequence ----------------
static inline void zero_buf(float* p, size_t nfloats) {
    size_t n4 = nfloats / 4;
    int blocks = (int)((n4 + 255) / 256);
    if (blocks > 8192) blocks = 8192;
    if (blocks < 1) blocks = 1;
    zero_kernel<<<blocks, 256>>>((float4*)p, n4);
}

extern "C" void kernel_launch(void* const* d_in, const int* in_sizes, int n_in,
                              void* d_out, int out_size) {
    const float* x   = (const float*)d_in[0];
    const int*   ei  = (const int*)d_in[1];   // int64 in reference -> delivered as int32
    const float* w1a = (const float*)d_in[2];  const float* b1a = (const float*)d_in[3];
    const float* w1b = (const float*)d_in[4];  const float* b1b = (const float*)d_in[5];
    const float* g1  = (const float*)d_in[6];  const float* be1 = (const float*)d_in[7];
    const float* w2a = (const float*)d_in[8];  const float* b2a = (const float*)d_in[9];
    const float* w2b = (const float*)d_in[10]; const float* b2b = (const float*)d_in[11];
    const float* g2  = (const float*)d_in[12]; const float* be2 = (const float*)d_in[13];
    const float* w3a = (const float*)d_in[14]; const float* b3a = (const float*)d_in[15];
    const float* w3b = (const float*)d_in[16]; const float* b3b = (const float*)d_in[17];
    const float* wfc = (const float*)d_in[18]; const float* bfc = (const float*)d_in[19];
    float* out = (float*)d_out;

    const int M = NODES;
    const int E = in_sizes[1] / 2;
    const int* src = ei;
    const int* dst = ei + E;

    float *agg, *z, *h, *bns, *bnq, *degf;
    cudaGetSymbolAddress((void**)&agg, g_agg);
    cudaGetSymbolAddress((void**)&z,   g_z);
    cudaGetSymbolAddress((void**)&h,   g_h);
    cudaGetSymbolAddress((void**)&bns, g_bnsum);
    cudaGetSymbolAddress((void**)&bnq, g_bnsq);
    cudaGetSymbolAddress((void**)&degf, g_deg);

    dim3 ggrid((M + 127) / 128, 4);   // N=256 -> 4 col tiles of 64
    const int EB = (E + 255) / 256;
    const int AGG_BLOCKS = 6250;      // 50000 warps, grid-stride over 100k nodes
    const int BN_BLOCKS = 512;

    // ---- build CSR (once; reused by all 3 layers) ----
    zero_buf(degf, NODES);            // 100000 ints = 25000 float4
    hist_kernel<<<EB, 256>>>(dst, E);
    scan_blocksum_kernel<<<SCAN_NB, 256>>>();
    scan_bases_kernel<<<1, 256>>>();
    scan_final_kernel<<<SCAN_NB, 256>>>();
    bucket_kernel<<<EB, 256>>>(src, dst, E);

    // ---- conv1 (K=128 aggregation on x) ----
    agg_kernel<128><<<AGG_BLOCKS, 256>>>(x, agg);
    gemm_tc_kernel<true,  true ><<<ggrid, 256>>>(x, agg, w1a, b1a, z, M, 128, 256);
    gemm_tc_kernel<false, true ><<<ggrid, 256>>>(z, nullptr, w1b, b1b, h, M, 256, 256);
    zero_buf(bns, DIMM); zero_buf(bnq, DIMM);
    bn_stats_kernel<<<BN_BLOCKS, 256>>>(h, M);
    bn_apply_kernel<<<4096, 256>>>(h, g1, be1, M);

    // ---- conv2 ----
    agg_kernel<256><<<AGG_BLOCKS, 256>>>(h, agg);
    gemm_tc_kernel<true,  true ><<<ggrid, 256>>>(h, agg, w2a, b2a, z, M, 256, 256);
    gemm_tc_kernel<false, true ><<<ggrid, 256>>>(z, nullptr, w2b, b2b, h, M, 256, 256);
    zero_buf(bns, DIMM); zero_buf(bnq, DIMM);
    bn_stats_kernel<<<BN_BLOCKS, 256>>>(h, M);
    bn_apply_kernel<<<4096, 256>>>(h, g2, be2, M);

    // ---- conv3 ----
    agg_kernel<256><<<AGG_BLOCKS, 256>>>(h, agg);
    gemm_tc_kernel<true,  true ><<<ggrid, 256>>>(h, agg, w3a, b3a, z, M, 256, 256);
    gemm_tc_kernel<false, true ><<<ggrid, 256>>>(z, nullptr, w3b, b3b, h, M, 256, 256);

    // ---- fc + log_softmax ----
    fc_lsm_kernel<<<(M + 7) / 8, 256>>>(h, wfc, bfc, out, M);
}